// round 8
// baseline (speedup 1.0000x reference)
#include <cuda_runtime.h>
#include <cuda_bf16.h>

// Problem constants: B=4, C=5, H=64, W=64, N=4096
#define BB 4
#define CC 5
#define WW 64
#define HW 4096
#define BSTRIDE 20480      // C*HW
#define NMAX 4096
#define M_BLK 16           // queries per attn block
#define NSPLIT 4           // p-range splits
#define NCHUNK 4           // 256-position chunks per split (4*256*4 = 4096)
#define LOG2E 1.4426950408889634f
#define KVBLKS 128         // kv blocks in prep (128 threads each)
#define PARTS_PER_B 32     // KVBLKS / BB

// -------- scratch (device globals; no allocation allowed) --------
__device__ float g_kf[BB * CC * HW];
__device__ float g_vf[BB * CC * HW];
__device__ float g_q[NMAX * CC];        // log2(e)-scaled query projections
__device__ int   g_perm[NMAX];
__device__ int   g_off[BB + 1];
__device__ int   g_blkoff[BB + 1];
__device__ float g_pmin[KVBLKS][CC];
__device__ float g_pmax[KVBLKS][CC];
__device__ float g_pnrm[KVBLKS];
__device__ float g_part[NSPLIT * NMAX * 6];   // per-split partials: [sum, o0..o4]

__device__ __forceinline__ float ex2f(float x) {
    float r; asm("ex2.approx.f32 %0, %1;" : "=f"(r) : "f"(x)); return r;
}

// ---------------------------------------------------------------
// Kernel 1 (fused), 128 threads/block:
//   blocks [0,128)            : k/v projection + y=x copy + per-block k stats
//   blocks [128,128+qblocks)  : q projection (log2-scaled)
//   last block                : deterministic rank-based sort by batch + block offsets
// ---------------------------------------------------------------
__global__ void prep_kernel(const float* __restrict__ x,
                            const float* __restrict__ qw, const float* __restrict__ qb,
                            const float* __restrict__ kw, const float* __restrict__ kb,
                            const float* __restrict__ vw, const float* __restrict__ vb,
                            const int* __restrict__ ib, const int* __restrict__ ih,
                            const int* __restrict__ iw, int n,
                            float* __restrict__ y) {
    int tid = threadIdx.x;
    if (blockIdx.x < KVBLKS) {
        __shared__ float skw[25], skb[5], svw[25], svb[5];
        __shared__ float smin[4][CC], smax[4][CC], snrm[4];
        if (tid < 25) { skw[tid] = kw[tid]; svw[tid] = vw[tid]; }
        if (tid < 5)  { skb[tid] = kb[tid]; svb[tid] = vb[tid]; }
        __syncthreads();

        int t = blockIdx.x * 128 + tid;
        int b = t >> 12;
        int p = t & (HW - 1);
        const float* xb = x + b * BSTRIDE + p;
        float* yb = y + b * BSTRIDE + p;

        float xs[CC];
#pragma unroll
        for (int c = 0; c < CC; c++) { xs[c] = xb[c * HW]; yb[c * HW] = xs[c]; }

        float kk[CC]; float nrm = 0.0f;
#pragma unroll
        for (int o = 0; o < CC; o++) {
            float k = skb[o], v = svb[o];
#pragma unroll
            for (int c = 0; c < CC; c++) {
                k = fmaf(skw[o * CC + c], xs[c], k);
                v = fmaf(svw[o * CC + c], xs[c], v);
            }
            g_kf[b * BSTRIDE + o * HW + p] = k;
            g_vf[b * BSTRIDE + o * HW + p] = v;
            kk[o] = k;
            nrm = fmaf(k, k, nrm);
        }

        float mn[CC], mx[CC];
#pragma unroll
        for (int c = 0; c < CC; c++) { mn[c] = kk[c]; mx[c] = kk[c]; }
#pragma unroll
        for (int off = 16; off > 0; off >>= 1) {
#pragma unroll
            for (int c = 0; c < CC; c++) {
                mn[c] = fminf(mn[c], __shfl_xor_sync(0xffffffffu, mn[c], off));
                mx[c] = fmaxf(mx[c], __shfl_xor_sync(0xffffffffu, mx[c], off));
            }
            nrm = fmaxf(nrm, __shfl_xor_sync(0xffffffffu, nrm, off));
        }
        int wid = tid >> 5, lane = tid & 31;
        if (lane == 0) {
#pragma unroll
            for (int c = 0; c < CC; c++) { smin[wid][c] = mn[c]; smax[wid][c] = mx[c]; }
            snrm[wid] = nrm;
        }
        __syncthreads();
        if (tid < CC) {
            float a = smin[0][tid], bx = smax[0][tid];
#pragma unroll
            for (int w = 1; w < 4; w++) { a = fminf(a, smin[w][tid]); bx = fmaxf(bx, smax[w][tid]); }
            g_pmin[blockIdx.x][tid] = a;
            g_pmax[blockIdx.x][tid] = bx;
        }
        if (tid == CC) {
            float a = snrm[0];
#pragma unroll
            for (int w = 1; w < 4; w++) a = fmaxf(a, snrm[w]);
            g_pnrm[blockIdx.x] = a;
        }
    } else if (blockIdx.x < gridDim.x - 1) {
        __shared__ float sw[25], sb[5];
        if (tid < 25) sw[tid] = qw[tid];
        if (tid < 5)  sb[tid] = qb[tid];
        __syncthreads();
        int i = (blockIdx.x - KVBLKS) * 128 + tid;
        if (i >= n) return;
        int b = ib[i];
        int pix = ih[i] * WW + iw[i];
        const float* xb = x + b * BSTRIDE + pix;
        float xs[CC];
#pragma unroll
        for (int c = 0; c < CC; c++) xs[c] = xb[c * HW];
#pragma unroll
        for (int o = 0; o < CC; o++) {
            float q = sb[o];
#pragma unroll
            for (int c = 0; c < CC; c++) q = fmaf(sw[o * CC + c], xs[c], q);
            g_q[i * CC + o] = q * LOG2E;
        }
    } else {
        // deterministic rank-based counting sort by batch (atomic-free)
        __shared__ int s_cnt[128][BB];
        __shared__ int s_tot[BB], s_base[BB];
        int c0 = 0, c1 = 0, c2 = 0, c3 = 0;
        for (int i = tid; i < n; i += 128) {
            int b = ib[i];
            c0 += (b == 0); c1 += (b == 1); c2 += (b == 2); c3 += (b == 3);
        }
        s_cnt[tid][0] = c0; s_cnt[tid][1] = c1; s_cnt[tid][2] = c2; s_cnt[tid][3] = c3;
        __syncthreads();
        if (tid < BB) {
            int run = 0;
            for (int j = 0; j < 128; j++) { int t = s_cnt[j][tid]; s_cnt[j][tid] = run; run += t; }
            s_tot[tid] = run;
        }
        __syncthreads();
        if (tid == 0) {
            int acc = 0, bacc = 0;
            for (int b = 0; b < BB; b++) {
                g_off[b] = acc; s_base[b] = acc; acc += s_tot[b];
                g_blkoff[b] = bacc; bacc += (s_tot[b] + M_BLK - 1) / M_BLK;
            }
            g_off[BB] = acc;
            g_blkoff[BB] = bacc;
        }
        __syncthreads();
        int cur[BB];
#pragma unroll
        for (int b = 0; b < BB; b++) cur[b] = s_base[b] + s_cnt[tid][b];
        for (int i = tid; i < n; i += 128) {
            int b = ib[i];
            g_perm[cur[b]++] = i;
        }
    }
}

// ---------------------------------------------------------------
// Kernel 2: smem-staged one-pass bounded-softmax attention.
// Block = 256 threads, M_BLK=16 queries of one batch, p-split over gridDim.y.
// k/v staged in double-buffered smem chunks (256 positions = 10KB/buffer);
// each warp computes 2 queries from the shared chunk -> low regs + high reuse.
// Block-uniform true upper bound (min(separable, Cauchy) - 32 log2) makes
// per-split partials combine by plain addition in the epilogue.
// ---------------------------------------------------------------
__global__ void __launch_bounds__(256, 3)
attn_kernel() {
    int tid = threadIdx.x;

    __shared__ int   s_boff[BB + 1], s_off[BB + 1];
    __shared__ int   s_n[M_BLK];
    __shared__ float s_kmn[CC], s_kmx[CC], s_knrm;
    __shared__ float2 sbuf[2][10][128];     // [buf][k0..k4,v0..v4][pair]

    if (tid < BB + 1) { s_boff[tid] = g_blkoff[tid]; s_off[tid] = g_off[tid]; }
    __syncthreads();

    int blk = blockIdx.x;
    if (blk >= s_boff[BB]) return;
    int b = 0;
    while (blk >= s_boff[b + 1]) b++;
    int base = s_off[b] + (blk - s_boff[b]) * M_BLK;
    int end = s_off[b + 1];
    int mcnt = min(M_BLK, end - base);
    int s = blockIdx.y;

    if (tid < M_BLK) s_n[tid] = (tid < mcnt) ? g_perm[base + tid] : -1;
    if (tid >= 32 && tid < 32 + CC) {
        int c = tid - 32;
        float a = 3.0e38f;
#pragma unroll
        for (int k = 0; k < PARTS_PER_B; k++) a = fminf(a, g_pmin[b * PARTS_PER_B + k][c]);
        s_kmn[c] = a;
    } else if (tid >= 64 && tid < 64 + CC) {
        int c = tid - 64;
        float a = -3.0e38f;
#pragma unroll
        for (int k = 0; k < PARTS_PER_B; k++) a = fmaxf(a, g_pmax[b * PARTS_PER_B + k][c]);
        s_kmx[c] = a;
    } else if (tid == 96) {
        float a = 0.0f;
#pragma unroll
        for (int k = 0; k < PARTS_PER_B; k++) a = fmaxf(a, g_pnrm[b * PARTS_PER_B + k]);
        s_knrm = sqrtf(a);
    }
    __syncthreads();

    int w = tid >> 5, lane = tid & 31;
    int n0 = s_n[2 * w], n1 = s_n[2 * w + 1];

    float q0[CC], q1[CC];
#pragma unroll
    for (int c = 0; c < CC; c++) {
        q0[c] = (n0 >= 0) ? __ldg(&g_q[n0 * CC + c]) : 0.0f;
        q1[c] = (n1 >= 0) ? __ldg(&g_q[n1 * CC + c]) : 0.0f;
    }
    float nl0, nl1;
    {
        float knrm = s_knrm;
        float sep0 = 0.0f, qq0 = 0.0f, sep1 = 0.0f, qq1 = 0.0f;
#pragma unroll
        for (int c = 0; c < CC; c++) {
            sep0 += fmaxf(q0[c] * s_kmx[c], q0[c] * s_kmn[c]);
            qq0 = fmaf(q0[c], q0[c], qq0);
            sep1 += fmaxf(q1[c] * s_kmx[c], q1[c] * s_kmn[c]);
            qq1 = fmaf(q1[c], q1[c], qq1);
        }
        nl0 = 32.0f - fminf(sep0, sqrtf(qq0) * knrm);
        nl1 = 32.0f - fminf(sep1, sqrtf(qq1) * knrm);
    }

    const float2* gk2 = (const float2*)g_kf + b * (BSTRIDE / 2);
    const float2* gv2 = (const float2*)g_vf + b * (BSTRIDE / 2);
    int pbase = s * (NCHUNK * 128);     // float2 offset of this split within a channel

    // preload chunk 0
    float2 pf[5];
#pragma unroll
    for (int j = 0; j < 5; j++) {
        int idx = j * 256 + tid; int ch = idx >> 7; int off = idx & 127;
        pf[j] = (ch < 5) ? gk2[ch * 2048 + pbase + off]
                         : gv2[(ch - 5) * 2048 + pbase + off];
    }
#pragma unroll
    for (int j = 0; j < 5; j++) {
        int idx = j * 256 + tid;
        sbuf[0][idx >> 7][idx & 127] = pf[j];
    }
    __syncthreads();

    float ssum0 = 0.0f, ssum1 = 0.0f;
    float oa0[CC], oa1[CC];
#pragma unroll
    for (int c = 0; c < CC; c++) { oa0[c] = 0.0f; oa1[c] = 0.0f; }

#pragma unroll 1
    for (int cidx = 0; cidx < NCHUNK; cidx++) {
        int cb = cidx & 1;
        if (cidx + 1 < NCHUNK) {
#pragma unroll
            for (int j = 0; j < 5; j++) {
                int idx = j * 256 + tid; int ch = idx >> 7; int off = idx & 127;
                int g = pbase + (cidx + 1) * 128 + off;
                pf[j] = (ch < 5) ? gk2[ch * 2048 + g] : gv2[(ch - 5) * 2048 + g];
            }
        }
#pragma unroll
        for (int pp = 0; pp < 4; pp++) {
            int pair = pp * 32 + lane;
            float2 k0 = sbuf[cb][0][pair];
            float2 k1 = sbuf[cb][1][pair];
            float2 k2 = sbuf[cb][2][pair];
            float2 k3 = sbuf[cb][3][pair];
            float2 k4 = sbuf[cb][4][pair];
            float2 v0 = sbuf[cb][5][pair];
            float2 v1 = sbuf[cb][6][pair];
            float2 v2 = sbuf[cb][7][pair];
            float2 v3 = sbuf[cb][8][pair];
            float2 v4 = sbuf[cb][9][pair];
            // m0
            {
                float ex = fmaf(q0[0], k0.x, nl0);
                ex = fmaf(q0[1], k1.x, ex);
                ex = fmaf(q0[2], k2.x, ex);
                ex = fmaf(q0[3], k3.x, ex);
                ex = fmaf(q0[4], k4.x, ex);
                float ey = fmaf(q0[0], k0.y, nl0);
                ey = fmaf(q0[1], k1.y, ey);
                ey = fmaf(q0[2], k2.y, ey);
                ey = fmaf(q0[3], k3.y, ey);
                ey = fmaf(q0[4], k4.y, ey);
                float wx = ex2f(ex), wy = ex2f(ey);
                ssum0 += wx + wy;
                oa0[0] = fmaf(wx, v0.x, fmaf(wy, v0.y, oa0[0]));
                oa0[1] = fmaf(wx, v1.x, fmaf(wy, v1.y, oa0[1]));
                oa0[2] = fmaf(wx, v2.x, fmaf(wy, v2.y, oa0[2]));
                oa0[3] = fmaf(wx, v3.x, fmaf(wy, v3.y, oa0[3]));
                oa0[4] = fmaf(wx, v4.x, fmaf(wy, v4.y, oa0[4]));
            }
            // m1
            {
                float ex = fmaf(q1[0], k0.x, nl1);
                ex = fmaf(q1[1], k1.x, ex);
                ex = fmaf(q1[2], k2.x, ex);
                ex = fmaf(q1[3], k3.x, ex);
                ex = fmaf(q1[4], k4.x, ex);
                float ey = fmaf(q1[0], k0.y, nl1);
                ey = fmaf(q1[1], k1.y, ey);
                ey = fmaf(q1[2], k2.y, ey);
                ey = fmaf(q1[3], k3.y, ey);
                ey = fmaf(q1[4], k4.y, ey);
                float wx = ex2f(ex), wy = ex2f(ey);
                ssum1 += wx + wy;
                oa1[0] = fmaf(wx, v0.x, fmaf(wy, v0.y, oa1[0]));
                oa1[1] = fmaf(wx, v1.x, fmaf(wy, v1.y, oa1[1]));
                oa1[2] = fmaf(wx, v2.x, fmaf(wy, v2.y, oa1[2]));
                oa1[3] = fmaf(wx, v3.x, fmaf(wy, v3.y, oa1[3]));
                oa1[4] = fmaf(wx, v4.x, fmaf(wy, v4.y, oa1[4]));
            }
        }
        if (cidx + 1 < NCHUNK) {
#pragma unroll
            for (int j = 0; j < 5; j++) {
                int idx = j * 256 + tid;
                sbuf[cb ^ 1][idx >> 7][idx & 127] = pf[j];
            }
        }
        __syncthreads();
    }

    // full-warp xor reduction (12 values)
#pragma unroll
    for (int off = 16; off > 0; off >>= 1) {
        ssum0 += __shfl_xor_sync(0xffffffffu, ssum0, off);
        ssum1 += __shfl_xor_sync(0xffffffffu, ssum1, off);
#pragma unroll
        for (int c = 0; c < CC; c++) {
            oa0[c] += __shfl_xor_sync(0xffffffffu, oa0[c], off);
            oa1[c] += __shfl_xor_sync(0xffffffffu, oa1[c], off);
        }
    }
    if (lane == 0 && n0 >= 0) {
        float* d = &g_part[(s * NMAX + n0) * 6];
        d[0] = ssum0;
#pragma unroll
        for (int c = 0; c < CC; c++) d[1 + c] = oa0[c];
    }
    if (lane == 1 && n1 >= 0) {
        float* d = &g_part[(s * NMAX + n1) * 6];
        d[0] = ssum1;
#pragma unroll
        for (int c = 0; c < CC; c++) d[1 + c] = oa1[c];
    }
}

// ---------------------------------------------------------------
// Kernel 3: epilogue — sum split partials, normalize, scatter into y.
// ---------------------------------------------------------------
__global__ void epi_kernel(const float* __restrict__ x,
                           const int* __restrict__ ib, const int* __restrict__ ih,
                           const int* __restrict__ iw,
                           const float* __restrict__ gamma,
                           float* __restrict__ y, int n) {
    int i = blockIdx.x * 128 + threadIdx.x;
    if (i >= n) return;
    float acc[6];
#pragma unroll
    for (int j = 0; j < 6; j++) acc[j] = 0.0f;
#pragma unroll
    for (int s = 0; s < NSPLIT; s++) {
        const float* p = &g_part[(s * NMAX + i) * 6];
#pragma unroll
        for (int j = 0; j < 6; j++) acc[j] += p[j];
    }
    float inv = 1.0f / acc[0];
    float g = gamma[0];
    int b = ib[i];
    int pix = ih[i] * WW + iw[i];
    int bse = b * BSTRIDE + pix;
#pragma unroll
    for (int c = 0; c < CC; c++)
        y[bse + c * HW] = fmaf(g, acc[1 + c] * inv, x[bse + c * HW]);
}

// ---------------------------------------------------------------
// launch
// ---------------------------------------------------------------
extern "C" void kernel_launch(void* const* d_in, const int* in_sizes, int n_in,
                              void* d_out, int out_size) {
    const float* x     = (const float*)d_in[0];
    const float* qw    = (const float*)d_in[2];
    const float* qb    = (const float*)d_in[3];
    const float* kw    = (const float*)d_in[4];
    const float* kb    = (const float*)d_in[5];
    const float* vw    = (const float*)d_in[6];
    const float* vb    = (const float*)d_in[7];
    const float* gamma = (const float*)d_in[8];
    const int*   ib    = (const int*)d_in[9];
    const int*   ih    = (const int*)d_in[10];
    const int*   iw    = (const int*)d_in[11];
    float* y = (float*)d_out;

    int n = in_sizes[9];
    int qblocks = (n + 127) / 128;

    prep_kernel<<<KVBLKS + qblocks + 1, 128>>>(x, qw, qb, kw, kb, vw, vb, ib, ih, iw, n, y);

    int maxmblk = (n + M_BLK - 1) / M_BLK + BB - 1;   // upper bound on m-blocks
    dim3 grid(maxmblk, NSPLIT);
    attn_kernel<<<grid, 256>>>();

    epi_kernel<<<(n + 127) / 128, 128>>>(x, ib, ih, iw, gamma, y, n);
}

// round 9
// speedup vs baseline: 1.1280x; 1.1280x over previous
#include <cuda_runtime.h>
#include <cuda_bf16.h>

// Problem constants: B=4, C=5, H=64, W=64, N=4096
#define BB 4
#define CC 5
#define WW 64
#define HW 4096
#define BSTRIDE 20480      // C*HW
#define NMAX 4096
#define M_TILE 6           // queries per attn block
#define LOG2E 1.4426950408889634f
#define KVBLKS 64          // kv blocks in prep (256 threads each)
#define PARTS_PER_B 16     // KVBLKS / BB

// -------- scratch (device globals; no allocation allowed) --------
__device__ float g_kf[BB * CC * HW];
__device__ float g_vf[BB * CC * HW];
__device__ float g_q[NMAX * CC];        // log2(e)-scaled query projections
__device__ int   g_perm[NMAX];
__device__ int   g_off[BB + 1];
__device__ int   g_blkoff[BB + 1];
__device__ float g_pmin[KVBLKS][CC];
__device__ float g_pmax[KVBLKS][CC];
__device__ float g_pnrm[KVBLKS];

__device__ __forceinline__ float ex2f(float x) {
    float r; asm("ex2.approx.f32 %0, %1;" : "=f"(r) : "f"(x)); return r;
}

// ---------------------------------------------------------------
// Kernel 1 (fused), 256 threads/block:
//   blocks [0,64)            : k/v projection + y=x copy + per-block k stats
//   blocks [64,64+qblocks)   : q projection (log2-scaled)
//   last block               : counting sort by batch (MLP-batched loads)
// ---------------------------------------------------------------
__global__ void prep_kernel(const float* __restrict__ x,
                            const float* __restrict__ qw, const float* __restrict__ qb,
                            const float* __restrict__ kw, const float* __restrict__ kb,
                            const float* __restrict__ vw, const float* __restrict__ vb,
                            const int* __restrict__ ib, const int* __restrict__ ih,
                            const int* __restrict__ iw, int n,
                            float* __restrict__ y) {
    int tid = threadIdx.x;
    if (blockIdx.x < KVBLKS) {
        __shared__ float skw[25], skb[5], svw[25], svb[5];
        __shared__ float smin[8][CC], smax[8][CC], snrm[8];
        if (tid < 25) { skw[tid] = kw[tid]; svw[tid] = vw[tid]; }
        if (tid < 5)  { skb[tid] = kb[tid]; svb[tid] = vb[tid]; }
        __syncthreads();

        int t = blockIdx.x * 256 + tid;
        int b = t >> 12;
        int p = t & (HW - 1);
        const float* xb = x + b * BSTRIDE + p;
        float* yb = y + b * BSTRIDE + p;

        float xs[CC];
#pragma unroll
        for (int c = 0; c < CC; c++) { xs[c] = xb[c * HW]; yb[c * HW] = xs[c]; }

        float kk[CC]; float nrm = 0.0f;
#pragma unroll
        for (int o = 0; o < CC; o++) {
            float k = skb[o], v = svb[o];
#pragma unroll
            for (int c = 0; c < CC; c++) {
                k = fmaf(skw[o * CC + c], xs[c], k);
                v = fmaf(svw[o * CC + c], xs[c], v);
            }
            g_kf[b * BSTRIDE + o * HW + p] = k;
            g_vf[b * BSTRIDE + o * HW + p] = v;
            kk[o] = k;
            nrm = fmaf(k, k, nrm);
        }

        float mn[CC], mx[CC];
#pragma unroll
        for (int c = 0; c < CC; c++) { mn[c] = kk[c]; mx[c] = kk[c]; }
#pragma unroll
        for (int off = 16; off > 0; off >>= 1) {
#pragma unroll
            for (int c = 0; c < CC; c++) {
                mn[c] = fminf(mn[c], __shfl_xor_sync(0xffffffffu, mn[c], off));
                mx[c] = fmaxf(mx[c], __shfl_xor_sync(0xffffffffu, mx[c], off));
            }
            nrm = fmaxf(nrm, __shfl_xor_sync(0xffffffffu, nrm, off));
        }
        int wid = tid >> 5, lane = tid & 31;
        if (lane == 0) {
#pragma unroll
            for (int c = 0; c < CC; c++) { smin[wid][c] = mn[c]; smax[wid][c] = mx[c]; }
            snrm[wid] = nrm;
        }
        __syncthreads();
        if (tid < CC) {
            float a = smin[0][tid], bx = smax[0][tid];
#pragma unroll
            for (int w = 1; w < 8; w++) { a = fminf(a, smin[w][tid]); bx = fmaxf(bx, smax[w][tid]); }
            g_pmin[blockIdx.x][tid] = a;
            g_pmax[blockIdx.x][tid] = bx;
        }
        if (tid == CC) {
            float a = snrm[0];
#pragma unroll
            for (int w = 1; w < 8; w++) a = fmaxf(a, snrm[w]);
            g_pnrm[blockIdx.x] = a;
        }
    } else if (blockIdx.x < gridDim.x - 1) {
        __shared__ float sw[25], sb[5];
        if (tid < 25) sw[tid] = qw[tid];
        if (tid < 5)  sb[tid] = qb[tid];
        __syncthreads();
        int i = (blockIdx.x - KVBLKS) * 256 + tid;
        if (i >= n) return;
        int b = ib[i];
        int pix = ih[i] * WW + iw[i];
        const float* xb = x + b * BSTRIDE + pix;
        float xs[CC];
#pragma unroll
        for (int c = 0; c < CC; c++) xs[c] = xb[c * HW];
#pragma unroll
        for (int o = 0; o < CC; o++) {
            float q = sb[o];
#pragma unroll
            for (int c = 0; c < CC; c++) q = fmaf(sw[o * CC + c], xs[c], q);
            g_q[i * CC + o] = q * LOG2E;
        }
    } else {
        // counting sort by batch; all loads MLP-batched up front.
        // Slot assignment order is numerically irrelevant (per-query compute
        // in attn is slot-independent), so atomic rank order is benign.
        __shared__ int scnt[BB], scur[BB];
        int myb[16];
#pragma unroll
        for (int j = 0; j < 16; j++) {
            int i = tid + j * 256;
            myb[j] = (i < n) ? ib[i] : -1;
        }
        if (tid < BB) scnt[tid] = 0;
        __syncthreads();
        int c0 = 0, c1 = 0, c2 = 0, c3 = 0;
#pragma unroll
        for (int j = 0; j < 16; j++) {
            c0 += (myb[j] == 0); c1 += (myb[j] == 1);
            c2 += (myb[j] == 2); c3 += (myb[j] == 3);
        }
        if (c0) atomicAdd(&scnt[0], c0);
        if (c1) atomicAdd(&scnt[1], c1);
        if (c2) atomicAdd(&scnt[2], c2);
        if (c3) atomicAdd(&scnt[3], c3);
        __syncthreads();
        if (tid == 0) {
            int acc = 0, bacc = 0;
            for (int b = 0; b < BB; b++) {
                int cnt = scnt[b];
                g_off[b] = acc; scur[b] = acc; acc += cnt;
                g_blkoff[b] = bacc; bacc += (cnt + M_TILE - 1) / M_TILE;
            }
            g_off[BB] = acc;
            g_blkoff[BB] = bacc;
        }
        __syncthreads();
#pragma unroll
        for (int j = 0; j < 16; j++) {
            int i = tid + j * 256;
            if (i < n) {
                int pos = atomicAdd(&scur[myb[j]], 1);
                g_perm[pos] = i;
            }
        }
    }
}

// ---------------------------------------------------------------
// Kernel 2: one-pass bounded-softmax attention with register
// double-buffered k/v prefetch. M_TILE=6 queries per 256-thread block.
// lmax = min(separable, Cauchy) true upper bound - 32 (log2 units),
// block-uniform per m -> no guard, no max alignment, plain sums.
// ---------------------------------------------------------------
#define LOADKV(kr, vr, idx)                                \
    do {                                                   \
        int _p = (idx);                                    \
        kr[0] = kf2[_p];                                   \
        kr[1] = kf2[2048 + _p];                            \
        kr[2] = kf2[2 * 2048 + _p];                        \
        kr[3] = kf2[3 * 2048 + _p];                        \
        kr[4] = kf2[4 * 2048 + _p];                        \
        vr[0] = vf2[_p];                                   \
        vr[1] = vf2[2048 + _p];                            \
        vr[2] = vf2[2 * 2048 + _p];                        \
        vr[3] = vf2[3 * 2048 + _p];                        \
        vr[4] = vf2[4 * 2048 + _p];                        \
    } while (0)

#define COMPUTEKV(kr, vr)                                              \
    do {                                                               \
        _Pragma("unroll")                                              \
        for (int m = 0; m < M_TILE; m++) {                             \
            float ex = fmaf(q[m][0], kr[0].x, nlmax[m]);               \
            ex = fmaf(q[m][1], kr[1].x, ex);                           \
            ex = fmaf(q[m][2], kr[2].x, ex);                           \
            ex = fmaf(q[m][3], kr[3].x, ex);                           \
            ex = fmaf(q[m][4], kr[4].x, ex);                           \
            float ey = fmaf(q[m][0], kr[0].y, nlmax[m]);               \
            ey = fmaf(q[m][1], kr[1].y, ey);                           \
            ey = fmaf(q[m][2], kr[2].y, ey);                           \
            ey = fmaf(q[m][3], kr[3].y, ey);                           \
            ey = fmaf(q[m][4], kr[4].y, ey);                           \
            float wx = ex2f(ex);                                       \
            float wy = ex2f(ey);                                       \
            ssum[m] += wx + wy;                                        \
            oacc[m][0] = fmaf(wx, vr[0].x, fmaf(wy, vr[0].y, oacc[m][0])); \
            oacc[m][1] = fmaf(wx, vr[1].x, fmaf(wy, vr[1].y, oacc[m][1])); \
            oacc[m][2] = fmaf(wx, vr[2].x, fmaf(wy, vr[2].y, oacc[m][2])); \
            oacc[m][3] = fmaf(wx, vr[3].x, fmaf(wy, vr[3].y, oacc[m][3])); \
            oacc[m][4] = fmaf(wx, vr[4].x, fmaf(wy, vr[4].y, oacc[m][4])); \
        }                                                              \
    } while (0)

__global__ void __launch_bounds__(256, 2)
attn_kernel(const float* __restrict__ x,
            const int* __restrict__ ih, const int* __restrict__ iw,
            const float* __restrict__ gamma, float* __restrict__ y) {
    int tid = threadIdx.x;

    __shared__ int   s_boff[BB + 1], s_off[BB + 1];
    __shared__ int   s_n[M_TILE];
    __shared__ float s_kmn[CC], s_kmx[CC], s_knrm;
    __shared__ float s_red[M_TILE * 6 * 8];

    if (tid < BB + 1) { s_boff[tid] = g_blkoff[tid]; s_off[tid] = g_off[tid]; }
    __syncthreads();

    int blk = blockIdx.x;
    if (blk >= s_boff[BB]) return;
    int b = 0;
    while (blk >= s_boff[b + 1]) b++;
    int base = s_off[b] + (blk - s_boff[b]) * M_TILE;
    int end = s_off[b + 1];
    int mcnt = min(M_TILE, end - base);

    if (tid < M_TILE) s_n[tid] = (tid < mcnt) ? g_perm[base + tid] : -1;
    // finalize per-batch k stats from PARTS_PER_B partials (cheap, per block)
    if (tid >= 32 && tid < 32 + CC) {
        int c = tid - 32;
        float a = 3.0e38f;
#pragma unroll
        for (int k = 0; k < PARTS_PER_B; k++) a = fminf(a, g_pmin[b * PARTS_PER_B + k][c]);
        s_kmn[c] = a;
    } else if (tid >= 64 && tid < 64 + CC) {
        int c = tid - 64;
        float a = -3.0e38f;
#pragma unroll
        for (int k = 0; k < PARTS_PER_B; k++) a = fmaxf(a, g_pmax[b * PARTS_PER_B + k][c]);
        s_kmx[c] = a;
    } else if (tid == 96) {
        float a = 0.0f;
#pragma unroll
        for (int k = 0; k < PARTS_PER_B; k++) a = fmaxf(a, g_pnrm[b * PARTS_PER_B + k]);
        s_knrm = sqrtf(a);
    }
    __syncthreads();

    float q[M_TILE][CC];
#pragma unroll
    for (int m = 0; m < M_TILE; m++) {
        int nq = s_n[m];
#pragma unroll
        for (int c = 0; c < CC; c++)
            q[m][c] = (nq >= 0) ? __ldg(&g_q[nq * CC + c]) : 0.0f;
    }

    // nlmax[m] = 32 - min(separable, Cauchy) upper bound (block-uniform)
    float nlmax[M_TILE];
    {
        float knrm = s_knrm;
#pragma unroll
        for (int m = 0; m < M_TILE; m++) {
            float sep = 0.0f, qq = 0.0f;
#pragma unroll
            for (int c = 0; c < CC; c++) {
                sep += fmaxf(q[m][c] * s_kmx[c], q[m][c] * s_kmn[c]);
                qq = fmaf(q[m][c], q[m][c], qq);
            }
            float cau = sqrtf(qq) * knrm;
            nlmax[m] = 32.0f - fminf(sep, cau);
        }
    }

    const float2* kf2 = (const float2*)(g_kf + b * BSTRIDE);
    const float2* vf2 = (const float2*)(g_vf + b * BSTRIDE);

    float ssum[M_TILE];
    float oacc[M_TILE][CC];
#pragma unroll
    for (int m = 0; m < M_TILE; m++) {
        ssum[m] = 0.0f;
#pragma unroll
        for (int c = 0; c < CC; c++) oacc[m][c] = 0.0f;
    }

    // register double-buffered sweep over 2048 float2 positions (8 iters)
    float2 kA[5], vA[5], kB[5], vB[5];
    LOADKV(kA, vA, tid);
#pragma unroll 1
    for (int it = 0; it < 8; it += 2) {
        LOADKV(kB, vB, tid + (it + 1) * 256);
        COMPUTEKV(kA, vA);
        if (it + 2 < 8) LOADKV(kA, vA, tid + (it + 2) * 256);
        COMPUTEKV(kB, vB);
    }

    int wid = tid >> 5, lane = tid & 31;

    // ---- sum reduction (bound uniform -> plain sums) ----
#pragma unroll
    for (int m = 0; m < M_TILE; m++) {
#pragma unroll
        for (int off = 16; off > 0; off >>= 1)
            ssum[m] += __shfl_xor_sync(0xffffffffu, ssum[m], off);
#pragma unroll
        for (int c = 0; c < CC; c++) {
#pragma unroll
            for (int off = 16; off > 0; off >>= 1)
                oacc[m][c] += __shfl_xor_sync(0xffffffffu, oacc[m][c], off);
        }
    }
    if (lane == 0) {
#pragma unroll
        for (int m = 0; m < M_TILE; m++) {
            s_red[(m * 6 + 0) * 8 + wid] = ssum[m];
#pragma unroll
            for (int c = 0; c < CC; c++)
                s_red[(m * 6 + 1 + c) * 8 + wid] = oacc[m][c];
        }
    }
    __syncthreads();

    if (tid < mcnt) {
        int m = tid;
        float s = 0.0f;
#pragma unroll
        for (int w = 0; w < 8; w++) s += s_red[(m * 6) * 8 + w];
        float inv = 1.0f / s;
        float g = gamma[0];
        int nq = s_n[m];
        int pix = ih[nq] * WW + iw[nq];
#pragma unroll
        for (int c = 0; c < CC; c++) {
            float oc = 0.0f;
#pragma unroll
            for (int w = 0; w < 8; w++) oc += s_red[(m * 6 + 1 + c) * 8 + w];
            int idx = b * BSTRIDE + c * HW + pix;
            y[idx] = fmaf(g, oc * inv, x[idx]);
        }
    }
}

// ---------------------------------------------------------------
// launch
// ---------------------------------------------------------------
extern "C" void kernel_launch(void* const* d_in, const int* in_sizes, int n_in,
                              void* d_out, int out_size) {
    const float* x     = (const float*)d_in[0];
    const float* qw    = (const float*)d_in[2];
    const float* qb    = (const float*)d_in[3];
    const float* kw    = (const float*)d_in[4];
    const float* kb    = (const float*)d_in[5];
    const float* vw    = (const float*)d_in[6];
    const float* vb    = (const float*)d_in[7];
    const float* gamma = (const float*)d_in[8];
    const int*   ib    = (const int*)d_in[9];
    const int*   ih    = (const int*)d_in[10];
    const int*   iw    = (const int*)d_in[11];
    float* y = (float*)d_out;

    int n = in_sizes[9];
    int qblocks = (n + 255) / 256;

    prep_kernel<<<KVBLKS + qblocks + 1, 256>>>(x, qw, qb, kw, kb, vw, vb, ib, ih, iw, n, y);

    int maxblk = (n + M_TILE - 1) / M_TILE + BB - 1;   // upper bound on working blocks
    attn_kernel<<<maxblk, 256>>>(x, ih, iw, gamma, y);
}